// round 14
// baseline (speedup 1.0000x reference)
#include <cuda_runtime.h>
#include <cuda_fp16.h>
#include <cstdint>

#define BB   8
#define MM   4096
#define NN   16384
#define HH   128
#define WW   128
#define BN   (BB*NN)
#define TAUF 0.01f
#define EPSF 1e-8f
#define ITERS 100

#define NSTAGES 8192        // both phases: 8192 stages of 64 cols
#define MAXSLOTS 2048       // 2 segments x up to 1024 CTAs

// smem: 3 slots x 18KB; slot = A 16KB + B 2KB
#define SLOT_A0   0
#define SLOT_B0   16384
#define SLOT_BYTES 18432
#define SM_TOTAL  (3 * SLOT_BYTES)     // 54 KB -> 4 CTAs/SM

// ---------------- device state (no allocations allowed) ----------------
__device__ __half g_Ah [(size_t)MM * NN];     // A fp16 row-major [i][j]
__device__ __half g_AhT[(size_t)MM * NN];     // A^T fp16 [j][i]
__device__ float  g_x[BN];
__device__ float  g_xbar[BN];
__device__ float  g_t[BN];
__device__ float  g_yb[2][2][BN];
__device__ __half g_t16[(size_t)16 * NN];     // rows 0-7 = hi(t), 8-15 = lo(t)*2048
__device__ __half g_r16[(size_t)16 * MM];     // rows 0-7 = hi(r), 8-15 = lo(r)*2048
__device__ float  g_rpart[(size_t)MAXSLOTS * 128 * 8];  // phase-1 partials [slot][rl][b]
__device__ float  g_gpart[(size_t)MAXSLOTS * 128 * 8];  // phase-2 partials [slot][rl][b]

// ---------------- helpers ----------------
#define SWZ(o) ((o) ^ (((o) >> 3) & 0x70))

#define CP16(DST, SRC) \
    asm volatile("cp.async.cg.shared.global [%0], [%1], 16;" :: "r"(DST), "l"(SRC))
#define CP_COMMIT() asm volatile("cp.async.commit_group;" ::: "memory")
#define CP_WAIT1()  asm volatile("cp.async.wait_group 1;"  ::: "memory")

#define LDM_X4(R0, R1, R2, R3, ADDR)                                          \
    asm volatile("ldmatrix.sync.aligned.m8n8.x4.shared.b16 {%0,%1,%2,%3}, [%4];" \
                 : "=r"(R0), "=r"(R1), "=r"(R2), "=r"(R3) : "r"(ADDR))

#define MMA16816(C, A0, A1, A2, A3, B0, B1)                                   \
    asm volatile("mma.sync.aligned.m16n8k16.row.col.f32.f16.f16.f32 "         \
                 "{%0,%1,%2,%3}, {%4,%5,%6,%7}, {%8,%9}, {%0,%1,%2,%3};"      \
                 : "+f"((C)[0]), "+f"((C)[1]), "+f"((C)[2]), "+f"((C)[3])     \
                 : "r"(A0), "r"(A1), "r"(A2), "r"(A3), "r"(B0), "r"(B1))

// ---------------- setup: A fp32 -> fp16 + fp16 transpose (one-time) ----------
__global__ void k_setup(const float* __restrict__ A) {
    __shared__ __half tile[32][33];
    int j0 = blockIdx.x * 32, i0 = blockIdx.y * 32;
    int tx = threadIdx.x, ty = threadIdx.y;          // (32, 8)
#pragma unroll
    for (int q = 0; q < 4; q++) {
        int il = ty + q * 8;
        float v = A[(size_t)(i0 + il) * NN + j0 + tx];
        __half h = __float2half_rn(v);
        g_Ah[(size_t)(i0 + il) * NN + j0 + tx] = h;
        tile[il][tx] = h;
    }
    __syncthreads();
#pragma unroll
    for (int q = 0; q < 4; q++) {
        int jl = ty + q * 8;
        g_AhT[(size_t)(j0 + jl) * MM + i0 + tx] = tile[tx][jl];
    }
}

// ---------------- zero init ----------------
__global__ void k_zero() {
    int idx = blockIdx.x * blockDim.x + threadIdx.x;
    if (idx < BN) {
        g_x[idx] = 0.f; g_xbar[idx] = 0.f;
        g_yb[0][0][idx] = 0.f; g_yb[0][1][idx] = 0.f;
    }
}

// ---------------- TV stencil + t16 hi/lo emit ----------------
__global__ void k_tv(int bi) {
    int idx = blockIdx.x * blockDim.x + threadIdx.x;
    if (idx >= BN) return;
    int p = idx & (NN - 1);
    int i = p >> 7;
    int j = p & 127;

    const float* yx = g_yb[bi][0];
    const float* yy = g_yb[bi][1];
    float*       oyx = g_yb[bi ^ 1][0];
    float*       oyy = g_yb[bi ^ 1][1];

    float yxv = yx[idx];
    float yyv = yy[idx];

    float dx = (j > 0) ? (yxv - yx[idx - 1])  : 0.f;
    float dy = (i > 0) ? (yyv - yy[idx - WW]) : 0.f;
    float t = g_x[idx] - TAUF * (dx + dy);
    g_t[idx] = t;

    __half hi = __float2half_rn(t);
    float  lo = (t - __half2float(hi)) * 2048.f;
    g_t16[idx] = hi;
    g_t16[(size_t)BN + idx] = __float2half_rn(lo);

    float xb = g_xbar[idx];
    float gx = (j < WW - 1) ? (xb - g_xbar[idx + 1])  : 0.f;
    float gy = (i < HH - 1) ? (xb - g_xbar[idx + WW]) : 0.f;

    float nyx = yxv + TAUF * gx;
    float nyy = yyv + TAUF * gy;
    float denom = fmaxf(fabsf(nyx), fabsf(nyy)) + EPSF;
    float inv = 1.f / denom;
    oyx[idx] = nyx * inv;
    oyy[idx] = nyy * inv;
}

// ---------------- unified HMMA GEMV kernel (static stage partition) ----------
// Global stage stream: stage gs in [0, 8192). Row-tile = gs >> tshift (128 rows),
// k-offset = (gs & tmask) * 64. CTA cta gets a contiguous range of q or q+1
// stages; flushes acc into slot 2*cta + seg at each row-tile boundary / end.
__global__ __launch_bounds__(128) void k_mma(int phase, int q, int rem) {
    extern __shared__ char sm[];
    unsigned smb = (unsigned)__cvta_generic_to_shared(sm);
    int tid = threadIdx.x, wid = tid >> 5, lane = tid & 31;
    int cta = blockIdx.x;

    const __half* Aop = phase ? g_AhT : g_Ah;
    const __half* Bop = phase ? g_r16 : g_t16;
    float*        outp = phase ? g_gpart : g_rpart;
    const int Ktot   = phase ? MM : NN;
    const int tshift = phase ? 6 : 8;
    const int tmask  = (1 << tshift) - 1;

    int thr   = rem * (q + 1);
    int start = (cta < rem) ? cta * (q + 1) : thr + (cta - rem) * q;
    int count = (cta < rem) ? q + 1 : q;
    int end   = start + count;

    // ---- stage fill: 9 x 16B cp.async per thread, one commit ----
    auto fill = [&](int gs, int slot) {
        unsigned slotb = smb + (unsigned)(slot * SLOT_BYTES);
        int tile = gs >> tshift;
        int koff = (gs & tmask) << 6;
        const __half* asrc = Aop + ((size_t)tile << 7) * Ktot + koff;
        const __half* bsrc = Bop + koff;
#pragma unroll
        for (int q8 = 0; q8 < 8; q8++) {
            int cc = tid + q8 * 128;              // 1024 chunks: row 0..127, c16 0..7
            int row = cc >> 3, c16 = cc & 7;
            unsigned off = (unsigned)(row * 128 + c16 * 16);
            CP16(slotb + SLOT_A0 + SWZ(off), asrc + (size_t)row * Ktot + c16 * 8);
        }
        int br = tid >> 3, bc = tid & 7;          // 128 chunks: row 0..15, c16 0..7
        unsigned boff = (unsigned)(br * 128 + bc * 16);
        CP16(slotb + SLOT_B0 + SWZ(boff), bsrc + (size_t)br * Ktot + bc * 8);
        CP_COMMIT();
    };

    float acc[2][2][4];
#pragma unroll
    for (int mt = 0; mt < 2; mt++)
#pragma unroll
        for (int nt = 0; nt < 2; nt++)
#pragma unroll
            for (int z = 0; z < 4; z++) acc[mt][nt][z] = 0.f;

    fill(start, 0);
    fill(start + 1, 1);

    int l8 = lane & 7;
    int lq = lane >> 3;
    int gfold = lane >> 2, t4 = lane & 3;
    const float is = 1.f / 2048.f;

    int sl = 0;       // slot of compute stage
    int slf = 2;      // slot of fill stage (gs+2)
    int seg = 0;

    for (int gs = start; gs < end; gs++) {
        CP_WAIT1();
        __syncthreads();                 // stage gs visible; stage gs-1 consumed

        if (gs + 2 < end) { fill(gs + 2, slf); } else { CP_COMMIT(); }
        slf = (slf == 2) ? 0 : slf + 1;

        unsigned slotb = smb + (unsigned)(sl * SLOT_BYTES);
        sl = (sl == 2) ? 0 : sl + 1;

        unsigned abase = slotb + SLOT_A0;
        unsigned bbase = slotb + SLOT_B0;

#pragma unroll
        for (int kk = 0; kk < 4; kk++) {
            unsigned brow = (lq >> 1) * 8 + l8;
            unsigned bcol = kk * 32 + (lq & 1) * 16;
            unsigned b0, b1, b2, b3;
            LDM_X4(b0, b1, b2, b3, bbase + SWZ(brow * 128 + bcol));

#pragma unroll
            for (int mt = 0; mt < 2; mt++) {
                unsigned arow = wid * 32 + mt * 16 + (lq & 1) * 8 + l8;
                unsigned acol = kk * 32 + (lq >> 1) * 16;
                unsigned a0, a1, a2, a3;
                LDM_X4(a0, a1, a2, a3, abase + SWZ(arow * 128 + acol));

                MMA16816(acc[mt][0], a0, a1, a2, a3, b0, b1);   // hi batches
                MMA16816(acc[mt][1], a0, a1, a2, a3, b2, b3);   // lo batches
            }
        }

        // flush at row-tile boundary or range end
        bool last = (gs + 1 == end) || (((gs + 1) >> tshift) != (gs >> tshift));
        if (last) {
            int slotid = 2 * cta + seg;
#pragma unroll
            for (int mt = 0; mt < 2; mt++) {
                int rl = wid * 32 + mt * 16 + gfold;
                float* d0 = outp + ((size_t)slotid * 128 + rl) * 8 + t4 * 2;
                float* d1 = outp + ((size_t)slotid * 128 + rl + 8) * 8 + t4 * 2;
                *reinterpret_cast<float2*>(d0) = make_float2(
                    acc[mt][0][0] + acc[mt][1][0] * is,
                    acc[mt][0][1] + acc[mt][1][1] * is);
                *reinterpret_cast<float2*>(d1) = make_float2(
                    acc[mt][0][2] + acc[mt][1][2] * is,
                    acc[mt][0][3] + acc[mt][1][3] * is);
            }
#pragma unroll
            for (int mt = 0; mt < 2; mt++)
#pragma unroll
                for (int nt = 0; nt < 2; nt++)
#pragma unroll
                    for (int z = 0; z < 4; z++) acc[mt][nt][z] = 0.f;
            seg++;
        }
    }
}

// ---------------- r prep: r = sum(rpart segs) - meas -> hi/lo fp16 -----------
__global__ void k_rprep(const float* __restrict__ meas, int q, int rem) {
    int idx = blockIdx.x * blockDim.x + threadIdx.x;   // 32768
    int i = idx >> 3, b = idx & 7;
    int tile = i >> 7, rl = i & 127;
    int gsa = tile << 8;                 // phase0: 256 stages per row-tile
    int thr = rem * (q + 1);

    int c0 = (gsa < thr) ? gsa / (q + 1) : rem + (gsa - thr) / q;
    int gsb = gsa + 255;
    int c1 = (gsb < thr) ? gsb / (q + 1) : rem + (gsb - thr) / q;

    float v = -meas[b * MM + i];
    for (int cc = c0; cc <= c1; cc++) {
        int st = (cc < rem) ? cc * (q + 1) : thr + (cc - rem) * q;
        int slot = 2 * cc + (st < gsa ? 1 : 0);
        v += g_rpart[((size_t)slot * 128 + rl) * 8 + b];
    }
    __half hi = __float2half_rn(v);
    float  lo = (v - __half2float(hi)) * 2048.f;
    g_r16[(size_t)b * MM + i] = hi;
    g_r16[(size_t)(b + 8) * MM + i] = __float2half_rn(lo);
}

// ---------------- finish: x = t - grad ; xbar = 2x - xbar_old ----------------
__global__ void k_fin(int q, int rem) {
    int idx = blockIdx.x * blockDim.x + threadIdx.x;
    if (idx >= BN) return;
    int b = idx >> 14;
    int j = idx & (NN - 1);
    int tile = j >> 7, rl = j & 127;
    int gsa = tile << 6;                 // phase1: 64 stages per row-tile
    int thr = rem * (q + 1);

    int c0 = (gsa < thr) ? gsa / (q + 1) : rem + (gsa - thr) / q;
    int gsb = gsa + 63;
    int c1 = (gsb < thr) ? gsb / (q + 1) : rem + (gsb - thr) / q;

    float s = 0.f;
    for (int cc = c0; cc <= c1; cc++) {
        int st = (cc < rem) ? cc * (q + 1) : thr + (cc - rem) * q;
        int slot = 2 * cc + (st < gsa ? 1 : 0);
        s += g_gpart[((size_t)slot * 128 + rl) * 8 + b];
    }
    float xn = g_t[idx] - s;
    float xbo = g_xbar[idx];
    g_x[idx] = xn;
    g_xbar[idx] = 2.f * xn - xbo;
}

// ---------------- output copy ----------------
__global__ void k_copy(float* __restrict__ out) {
    int idx = blockIdx.x * blockDim.x + threadIdx.x;
    if (idx < BN) out[idx] = g_x[idx];
}

// ---------------- launch ----------------
extern "C" void kernel_launch(void* const* d_in, const int* in_sizes, int n_in,
                              void* d_out, int out_size) {
    const float* meas = (const float*)d_in[0];
    const float* A    = (const float*)d_in[1];
    if (n_in >= 2 && in_sizes[0] != BB * MM) {
        meas = (const float*)d_in[1];
        A    = (const float*)d_in[0];
    }
    float* out = (float*)d_out;

    int nsm = 148;
    cudaDeviceGetAttribute(&nsm, cudaDevAttrMultiProcessorCount, 0);
    int ncta = 4 * nsm;
    if (ncta > MAXSLOTS / 2) ncta = MAXSLOTS / 2;
    int q   = NSTAGES / ncta;
    int rem = NSTAGES % ncta;

    cudaFuncSetAttribute(k_mma, cudaFuncAttributeMaxDynamicSharedMemorySize, SM_TOTAL);

    k_setup<<<dim3(NN / 32, MM / 32), dim3(32, 8)>>>(A);
    k_zero<<<BN / 256, 256>>>();

    for (int it = 0; it < ITERS; it++) {
        int bi = it & 1;
        k_tv<<<BN / 256, 256>>>(bi);
        k_mma<<<ncta, 128, SM_TOTAL>>>(0, q, rem);
        k_rprep<<<(MM * 8) / 256, 256>>>(meas, q, rem);
        k_mma<<<ncta, 128, SM_TOTAL>>>(1, q, rem);
        k_fin<<<BN / 256, 256>>>(q, rem);
    }
    k_copy<<<BN / 256, 256>>>(out);
}

// round 15
// speedup vs baseline: 1.1379x; 1.1379x over previous
#include <cuda_runtime.h>
#include <cuda_fp16.h>
#include <cstdint>

#define BB   8
#define MM   4096
#define NN   16384
#define HH   128
#define WW   128
#define BN   (BB*NN)
#define TAUF 0.01f
#define EPSF 1e-8f
#define ITERS 100

#define KC1    8            // phase-1 K chunks (16384/8 = 2048)
#define KC2    2            // phase-2 K chunks (4096/2 = 2048)
#define KCHUNK 2048
#define NSTEPS 16           // KCHUNK / 128 cols per stage

// smem: 3 slots x 36KB; slot = A[2 subtiles][16KB] + B[2 subtiles][2KB]
#define SLOT_A0   0
#define SLOT_A1   16384
#define SLOT_B0   32768
#define SLOT_B1   34816
#define SLOT_BYTES 36864
#define SM_TOTAL  (3 * SLOT_BYTES)     // 108 KB -> 2 CTAs/SM

// ---------------- device state (no allocations allowed) ----------------
__device__ __half g_Ah [(size_t)MM * NN];     // A fp16 row-major [i][j]
__device__ __half g_AhT[(size_t)MM * NN];     // A^T fp16 [j][i]
__device__ float  g_x[BN];
__device__ float  g_xbar[BN];
__device__ float  g_t[BN];
__device__ float  g_yb[2][2][BN];
__device__ __half g_t16[(size_t)16 * NN];     // rows 0-7 = hi(t), 8-15 = lo(t)*2048
__device__ __half g_r16[(size_t)16 * MM];     // rows 0-7 = hi(r), 8-15 = lo(r)*2048
__device__ float  g_rpart[(size_t)KC1 * MM * 8];   // phase-1 partials [kc][i][b]
__device__ float  g_gpart[(size_t)KC2 * NN * 8];   // phase-2 partials [kc][j][b]

// ---------------- helpers ----------------
#define SWZ(o) ((o) ^ (((o) >> 3) & 0x70))

#define CP16(DST, SRC) \
    asm volatile("cp.async.cg.shared.global [%0], [%1], 16;" :: "r"(DST), "l"(SRC))
#define CP_COMMIT() asm volatile("cp.async.commit_group;" ::: "memory")
#define CP_WAIT1()  asm volatile("cp.async.wait_group 1;"  ::: "memory")

#define LDM_X4(R0, R1, R2, R3, ADDR)                                          \
    asm volatile("ldmatrix.sync.aligned.m8n8.x4.shared.b16 {%0,%1,%2,%3}, [%4];" \
                 : "=r"(R0), "=r"(R1), "=r"(R2), "=r"(R3) : "r"(ADDR))

#define MMA16816(C, A0, A1, A2, A3, B0, B1)                                   \
    asm volatile("mma.sync.aligned.m16n8k16.row.col.f32.f16.f16.f32 "         \
                 "{%0,%1,%2,%3}, {%4,%5,%6,%7}, {%8,%9}, {%0,%1,%2,%3};"      \
                 : "+f"((C)[0]), "+f"((C)[1]), "+f"((C)[2]), "+f"((C)[3])     \
                 : "r"(A0), "r"(A1), "r"(A2), "r"(A3), "r"(B0), "r"(B1))

// ---------------- setup: A fp32 -> fp16 + fp16 transpose (one-time) ----------
__global__ void k_setup(const float* __restrict__ A) {
    __shared__ __half tile[32][33];
    int j0 = blockIdx.x * 32, i0 = blockIdx.y * 32;
    int tx = threadIdx.x, ty = threadIdx.y;          // (32, 8)
#pragma unroll
    for (int q = 0; q < 4; q++) {
        int il = ty + q * 8;
        float v = A[(size_t)(i0 + il) * NN + j0 + tx];
        __half h = __float2half_rn(v);
        g_Ah[(size_t)(i0 + il) * NN + j0 + tx] = h;
        tile[il][tx] = h;
    }
    __syncthreads();
#pragma unroll
    for (int q = 0; q < 4; q++) {
        int jl = ty + q * 8;
        g_AhT[(size_t)(j0 + jl) * MM + i0 + tx] = tile[tx][jl];
    }
}

// ---------------- zero init ----------------
__global__ void k_zero() {
    int idx = blockIdx.x * blockDim.x + threadIdx.x;
    if (idx < BN) {
        g_x[idx] = 0.f; g_xbar[idx] = 0.f;
        g_yb[0][0][idx] = 0.f; g_yb[0][1][idx] = 0.f;
    }
}

// ---------------- TV stencil + t16 hi/lo emit ----------------
__global__ void k_tv(int bi) {
    int idx = blockIdx.x * blockDim.x + threadIdx.x;
    if (idx >= BN) return;
    int p = idx & (NN - 1);
    int i = p >> 7;
    int j = p & 127;

    const float* yx = g_yb[bi][0];
    const float* yy = g_yb[bi][1];
    float*       oyx = g_yb[bi ^ 1][0];
    float*       oyy = g_yb[bi ^ 1][1];

    float yxv = yx[idx];
    float yyv = yy[idx];

    float dx = (j > 0) ? (yxv - yx[idx - 1])  : 0.f;
    float dy = (i > 0) ? (yyv - yy[idx - WW]) : 0.f;
    float t = g_x[idx] - TAUF * (dx + dy);
    g_t[idx] = t;

    __half hi = __float2half_rn(t);
    float  lo = (t - __half2float(hi)) * 2048.f;
    g_t16[idx] = hi;
    g_t16[(size_t)BN + idx] = __float2half_rn(lo);

    float xb = g_xbar[idx];
    float gx = (j < WW - 1) ? (xb - g_xbar[idx + 1])  : 0.f;
    float gy = (i < HH - 1) ? (xb - g_xbar[idx + WW]) : 0.f;

    float nyx = yxv + TAUF * gx;
    float nyy = yyv + TAUF * gy;
    float denom = fmaxf(fabsf(nyx), fabsf(nyy)) + EPSF;
    float inv = 1.f / denom;
    oyx[idx] = nyx * inv;
    oyy[idx] = nyy * inv;
}

// ---------------- unified HMMA GEMV kernel -----------------------------------
// phase 0: D[i,b16] += A[i,k]  * t16[b16,k]  (g_Ah,  K=NN, M=MM, grid (32,KC1))
// phase 1: D[j,b16] += AT[j,k] * r16[b16,k]  (g_AhT, K=MM, M=NN, grid (128,KC2))
// CTA: 128 rows x 2048-col K chunk = 16 stages of 128 cols; 256 threads,
// 8 warps x 16 rows. Stage = TWO 64-col sub-tiles: A 2x16KB SW128, B 2x2KB.
// 3-slot ring, cp.async wait_group 1, one __syncthreads per stage.
__global__ __launch_bounds__(256) void k_mma(int phase) {
    extern __shared__ char sm[];
    unsigned smb = (unsigned)__cvta_generic_to_shared(sm);
    int tid = threadIdx.x, wid = tid >> 5, lane = tid & 31;

    const __half* Aop = phase ? g_AhT : g_Ah;
    const __half* Bop = phase ? g_r16 : g_t16;
    float*        outp = phase ? g_gpart : g_rpart;
    const int Ktot = phase ? MM : NN;
    const int Mtot = phase ? NN : MM;

    int r0 = blockIdx.x * 128;
    int k0 = blockIdx.y * KCHUNK;

    // ---- stage fill: A 4 chunks/thread/half + B 1 chunk/thread, one commit ----
    auto fill = [&](int s) {
        unsigned slotb = smb + (unsigned)((s % 3) * SLOT_BYTES);
#pragma unroll
        for (int half = 0; half < 2; half++) {
            const __half* asrc = Aop + (size_t)r0 * Ktot + k0 + s * 128 + half * 64;
            unsigned abase = slotb + (half ? SLOT_A1 : SLOT_A0);
#pragma unroll
            for (int q = 0; q < 4; q++) {
                int cc = tid + q * 256;           // 1024 chunks: row 0..127, c16 0..7
                int row = cc >> 3, c16 = cc & 7;
                unsigned off = (unsigned)(row * 128 + c16 * 16);
                CP16(abase + SWZ(off), asrc + (size_t)row * Ktot + c16 * 8);
            }
        }
        // B: 256 chunks total (2 halves x 128); one per thread
        {
            int half = tid >> 7;
            int idx = tid & 127;
            const __half* bsrc = Bop + k0 + s * 128 + half * 64;
            int br = idx >> 3, bc = idx & 7;      // row 0..15, c16 0..7
            unsigned boff = (unsigned)(br * 128 + bc * 16);
            CP16(slotb + (half ? SLOT_B1 : SLOT_B0) + SWZ(boff),
                 bsrc + (size_t)br * Ktot + bc * 8);
        }
        CP_COMMIT();
    };

    float acc[2][4];
#pragma unroll
    for (int nt = 0; nt < 2; nt++)
#pragma unroll
        for (int z = 0; z < 4; z++) acc[nt][z] = 0.f;

    fill(0); fill(1);

    int l8 = lane & 7;
    int lq = lane >> 3;                  // ldmatrix quadrant 0..3

    for (int s = 0; s < NSTEPS; s++) {
        CP_WAIT1();
        __syncthreads();                 // stage s visible; stage s-1 consumed

        int ns = s + 2;
        if (ns < NSTEPS) { fill(ns); } else { CP_COMMIT(); }

        unsigned slotb = smb + (unsigned)((s % 3) * SLOT_BYTES);

#pragma unroll
        for (int kk = 0; kk < 8; kk++) {
            unsigned abase = slotb + ((kk < 4) ? SLOT_A0 : SLOT_A1);
            unsigned bbase = slotb + ((kk < 4) ? SLOT_B0 : SLOT_B1);
            int k4 = kk & 3;

            // B frags: [n0-7,k0-7],[n0-7,k8-15],[n8-15,k0-7],[n8-15,k8-15]
            unsigned brow = (lq >> 1) * 8 + l8;
            unsigned bcol = k4 * 32 + (lq & 1) * 16;
            unsigned b0, b1, b2, b3;
            LDM_X4(b0, b1, b2, b3, bbase + SWZ(brow * 128 + bcol));

            // A frags for this warp's 16 rows
            unsigned arow = wid * 16 + (lq & 1) * 8 + l8;
            unsigned acol = k4 * 32 + (lq >> 1) * 16;
            unsigned a0, a1, a2, a3;
            LDM_X4(a0, a1, a2, a3, abase + SWZ(arow * 128 + acol));

            MMA16816(acc[0], a0, a1, a2, a3, b0, b1);   // hi batches
            MMA16816(acc[1], a0, a1, a2, a3, b2, b3);   // lo batches
        }
    }

    // ---- epilogue: fold hi + lo/2048, write partials ----
    int g = lane >> 2, t4 = lane & 3;
    int row = r0 + wid * 16 + g;
    const float is = 1.f / 2048.f;
    float* d0 = outp + ((size_t)blockIdx.y * Mtot + row) * 8 + t4 * 2;
    float* d1 = outp + ((size_t)blockIdx.y * Mtot + row + 8) * 8 + t4 * 2;
    *reinterpret_cast<float2*>(d0) = make_float2(
        acc[0][0] + acc[1][0] * is, acc[0][1] + acc[1][1] * is);
    *reinterpret_cast<float2*>(d1) = make_float2(
        acc[0][2] + acc[1][2] * is, acc[0][3] + acc[1][3] * is);
}

// ---------------- r prep: r = sum(rpart) - meas -> hi/lo fp16 ----------------
__global__ void k_rprep(const float* __restrict__ meas) {
    int idx = blockIdx.x * blockDim.x + threadIdx.x;   // 32768
    int i = idx >> 3, b = idx & 7;
    float v = -meas[b * MM + i];
#pragma unroll
    for (int kc = 0; kc < KC1; kc++)
        v += g_rpart[((size_t)kc * MM + i) * 8 + b];
    __half hi = __float2half_rn(v);
    float  lo = (v - __half2float(hi)) * 2048.f;
    g_r16[(size_t)b * MM + i] = hi;
    g_r16[(size_t)(b + 8) * MM + i] = __float2half_rn(lo);
}

// ---------------- finish: x = t - grad ; xbar = 2x - xbar_old ----------------
__global__ void k_fin() {
    int idx = blockIdx.x * blockDim.x + threadIdx.x;
    if (idx >= BN) return;
    int b = idx >> 14;
    int j = idx & (NN - 1);
    float s = 0.f;
#pragma unroll
    for (int kc = 0; kc < KC2; kc++)
        s += g_gpart[((size_t)kc * NN + j) * 8 + b];
    float xn = g_t[idx] - s;
    float xbo = g_xbar[idx];
    g_x[idx] = xn;
    g_xbar[idx] = 2.f * xn - xbo;
}

// ---------------- output copy ----------------
__global__ void k_copy(float* __restrict__ out) {
    int idx = blockIdx.x * blockDim.x + threadIdx.x;
    if (idx < BN) out[idx] = g_x[idx];
}

// ---------------- launch ----------------
extern "C" void kernel_launch(void* const* d_in, const int* in_sizes, int n_in,
                              void* d_out, int out_size) {
    const float* meas = (const float*)d_in[0];
    const float* A    = (const float*)d_in[1];
    if (n_in >= 2 && in_sizes[0] != BB * MM) {
        meas = (const float*)d_in[1];
        A    = (const float*)d_in[0];
    }
    float* out = (float*)d_out;

    cudaFuncSetAttribute(k_mma, cudaFuncAttributeMaxDynamicSharedMemorySize, SM_TOTAL);

    k_setup<<<dim3(NN / 32, MM / 32), dim3(32, 8)>>>(A);
    k_zero<<<BN / 256, 256>>>();

    for (int it = 0; it < ITERS; it++) {
        int bi = it & 1;
        k_tv<<<BN / 256, 256>>>(bi);
        k_mma<<<dim3(MM / 128, KC1), 256, SM_TOTAL>>>(0);
        k_rprep<<<(MM * 8) / 256, 256>>>(meas);
        k_mma<<<dim3(NN / 128, KC2), 256, SM_TOTAL>>>(1);
        k_fin<<<BN / 256, 256>>>();
    }
    k_copy<<<BN / 256, 256>>>(out);
}

// round 16
// speedup vs baseline: 1.1549x; 1.0150x over previous
#include <cuda_runtime.h>
#include <cuda_fp16.h>
#include <cstdint>

#define BB   8
#define MM   4096
#define NN   16384
#define HH   128
#define WW   128
#define BN   (BB*NN)
#define TAUF 0.01f
#define EPSF 1e-8f
#define ITERS 100

#define KC1    8            // phase-1 K chunks (16384/8 = 2048)
#define KC2    2            // phase-2 K chunks (4096/2 = 2048)
#define KCHUNK 2048
#define NSTEPS 16           // KCHUNK / 128 cols per stage

// smem: 3 slots x 36KB; slot = A 32KB (2 subtiles contiguous) + B 4KB
#define SLOT_A0   0
#define SLOT_A1   16384
#define SLOT_B0   32768
#define SLOT_B1   34816
#define SLOT_BYTES 36864
#define SM_TOTAL  (3 * SLOT_BYTES)     // 108 KB -> 2 CTAs/SM

// ---------------- device state (no allocations allowed) ----------------
// A stored as pre-swizzled 16KB sub-tile blocks, consumption order:
//   g_Ah : block (rt, st) = rt*256 + st; rt in [0,32), st in [0,256)
//   g_AhT: block (rt, st) = rt*64  + st; rt in [0,128), st in [0,64)
__device__ __half g_Ah [(size_t)MM * NN];
__device__ __half g_AhT[(size_t)MM * NN];
__device__ float  g_x[BN];
__device__ float  g_xbar[BN];
__device__ float  g_t[BN];
__device__ float  g_yb[2][2][BN];
// B stored as pre-swizzled 2KB blocks (16 rows x 64 cols): t16: 256 blocks, r16: 64
__device__ __half g_t16[(size_t)16 * NN];
__device__ __half g_r16[(size_t)16 * MM];
__device__ float  g_rpart[(size_t)KC1 * MM * 8];   // [kc][i][b]
__device__ float  g_gpart[(size_t)KC2 * NN * 8];   // [kc][j][b]

// ---------------- helpers ----------------
#define SWZ(o) ((o) ^ (((o) >> 3) & 0x70))

#define CP16(DST, SRC) \
    asm volatile("cp.async.cg.shared.global [%0], [%1], 16;" :: "r"(DST), "l"(SRC))
#define CP_COMMIT() asm volatile("cp.async.commit_group;" ::: "memory")
#define CP_WAIT1()  asm volatile("cp.async.wait_group 1;"  ::: "memory")

#define LDM_X4(R0, R1, R2, R3, ADDR)                                          \
    asm volatile("ldmatrix.sync.aligned.m8n8.x4.shared.b16 {%0,%1,%2,%3}, [%4];" \
                 : "=r"(R0), "=r"(R1), "=r"(R2), "=r"(R3) : "r"(ADDR))

#define MMA16816(C, A0, A1, A2, A3, B0, B1)                                   \
    asm volatile("mma.sync.aligned.m16n8k16.row.col.f32.f16.f16.f32 "         \
                 "{%0,%1,%2,%3}, {%4,%5,%6,%7}, {%8,%9}, {%0,%1,%2,%3};"      \
                 : "+f"((C)[0]), "+f"((C)[1]), "+f"((C)[2]), "+f"((C)[3])     \
                 : "r"(A0), "r"(A1), "r"(A2), "r"(A3), "r"(B0), "r"(B1))

__device__ __forceinline__ uint4 pack8h(float4 f0, float4 f1) {
    __half2 h0 = __floats2half2_rn(f0.x, f0.y);
    __half2 h1 = __floats2half2_rn(f0.z, f0.w);
    __half2 h2 = __floats2half2_rn(f1.x, f1.y);
    __half2 h3 = __floats2half2_rn(f1.z, f1.w);
    uint4 o;
    o.x = *reinterpret_cast<unsigned*>(&h0);
    o.y = *reinterpret_cast<unsigned*>(&h1);
    o.z = *reinterpret_cast<unsigned*>(&h2);
    o.w = *reinterpret_cast<unsigned*>(&h3);
    return o;
}

// ---------------- setup: A fp32 -> staged swizzled fp16 blocks ---------------
// grid (256 st, 32 rt), 256 threads; thread: row r = t>>1, 32 cols.
__global__ void k_setupA(const float* __restrict__ A) {
    int st = blockIdx.x, rt = blockIdx.y, t = threadIdx.x;
    int r = t >> 1;
    int cbase = (t & 1) * 32;
    const float* src = A + (size_t)(rt * 128 + r) * NN + st * 64 + cbase;
    char* dst = (char*)g_Ah + ((size_t)(rt * 256 + st) << 14);
#pragma unroll
    for (int cg = 0; cg < 4; cg++) {
        float4 f0 = *reinterpret_cast<const float4*>(src + cg * 8);
        float4 f1 = *reinterpret_cast<const float4*>(src + cg * 8 + 4);
        int c0 = cbase + cg * 8;
        *reinterpret_cast<uint4*>(dst + SWZ((unsigned)(r * 128 + ((c0 >> 3) << 4)))) =
            pack8h(f0, f1);
    }
}

// grid (64 st, 128 rt), 256 threads; smem-transposed. Block element (r,c) =
// A[st*64 + c][rt*128 + r].
__global__ void k_setupAT(const float* __restrict__ A) {
    __shared__ __half tile[64][132];
    int st = blockIdx.x, rt = blockIdx.y, t = threadIdx.x;
    int jl = t >> 2;                 // source row 0..63
    int iq = (t & 3) * 32;           // i offset
    const float* src = A + (size_t)(st * 64 + jl) * NN + rt * 128 + iq;
#pragma unroll
    for (int g = 0; g < 8; g++) {
        float4 f = *reinterpret_cast<const float4*>(src + g * 4);
        tile[jl][iq + g * 4 + 0] = __float2half_rn(f.x);
        tile[jl][iq + g * 4 + 1] = __float2half_rn(f.y);
        tile[jl][iq + g * 4 + 2] = __float2half_rn(f.z);
        tile[jl][iq + g * 4 + 3] = __float2half_rn(f.w);
    }
    __syncthreads();
    char* dst = (char*)g_AhT + ((size_t)(rt * 64 + st) << 14);
#pragma unroll
    for (int qq = 0; qq < 4; qq++) {
        int id = t + qq * 256;
        int r = id >> 3, c16 = id & 7;
        float4 f0, f1;
        f0.x = __half2float(tile[c16 * 8 + 0][r]);
        f0.y = __half2float(tile[c16 * 8 + 1][r]);
        f0.z = __half2float(tile[c16 * 8 + 2][r]);
        f0.w = __half2float(tile[c16 * 8 + 3][r]);
        f1.x = __half2float(tile[c16 * 8 + 4][r]);
        f1.y = __half2float(tile[c16 * 8 + 5][r]);
        f1.z = __half2float(tile[c16 * 8 + 6][r]);
        f1.w = __half2float(tile[c16 * 8 + 7][r]);
        *reinterpret_cast<uint4*>(dst + SWZ((unsigned)(r * 128 + c16 * 16))) =
            pack8h(f0, f1);
    }
}

// ---------------- zero init ----------------
__global__ void k_zero() {
    int idx = blockIdx.x * blockDim.x + threadIdx.x;
    if (idx < BN) {
        g_x[idx] = 0.f; g_xbar[idx] = 0.f;
        g_yb[0][0][idx] = 0.f; g_yb[0][1][idx] = 0.f;
    }
}

// ---------------- TV stencil + staged t16 hi/lo emit ----------------
__global__ void k_tv(int bi) {
    int idx = blockIdx.x * blockDim.x + threadIdx.x;
    if (idx >= BN) return;
    int p = idx & (NN - 1);
    int i = p >> 7;
    int j = p & 127;
    int b = idx >> 14;

    const float* yx = g_yb[bi][0];
    const float* yy = g_yb[bi][1];
    float*       oyx = g_yb[bi ^ 1][0];
    float*       oyy = g_yb[bi ^ 1][1];

    float yxv = yx[idx];
    float yyv = yy[idx];

    float dx = (j > 0) ? (yxv - yx[idx - 1])  : 0.f;
    float dy = (i > 0) ? (yyv - yy[idx - WW]) : 0.f;
    float t = g_x[idx] - TAUF * (dx + dy);
    g_t[idx] = t;

    __half hi = __float2half_rn(t);
    float  lo = (t - __half2float(hi)) * 2048.f;
    // staged write: block = p>>6 (2KB), row b (hi) / b+8 (lo), col c = p&63
    int c = p & 63;
    char* blk = (char*)g_t16 + ((size_t)(p >> 6) << 11);
    unsigned cpart = (unsigned)(((c >> 3) << 4));
    *reinterpret_cast<__half*>(blk + SWZ((unsigned)(b * 128) + cpart) + (c & 7) * 2) = hi;
    *reinterpret_cast<__half*>(blk + SWZ((unsigned)((b + 8) * 128) + cpart) + (c & 7) * 2) =
        __float2half_rn(lo);

    float xb = g_xbar[idx];
    float gx = (j < WW - 1) ? (xb - g_xbar[idx + 1])  : 0.f;
    float gy = (i < HH - 1) ? (xb - g_xbar[idx + WW]) : 0.f;

    float nyx = yxv + TAUF * gx;
    float nyy = yyv + TAUF * gy;
    float denom = fmaxf(fabsf(nyx), fabsf(nyy)) + EPSF;
    float inv = 1.f / denom;
    oyx[idx] = nyx * inv;
    oyy[idx] = nyy * inv;
}

// ---------------- unified HMMA GEMV kernel -----------------------------------
// Identical consumption to R15 (256 thr, 8 warps x 16 rows, 3-slot ring).
// Fill is now a LINEAR copy: A = one contiguous 32KB block pair; B = 4KB pair.
__global__ __launch_bounds__(256) void k_mma(int phase) {
    extern __shared__ char sm[];
    unsigned smb = (unsigned)__cvta_generic_to_shared(sm);
    int tid = threadIdx.x, wid = tid >> 5, lane = tid & 31;

    const __half* Aop = phase ? g_AhT : g_Ah;
    const __half* Bop = phase ? g_r16 : g_t16;
    float*        outp = phase ? g_gpart : g_rpart;
    const int Mtot = phase ? NN : MM;
    const int nst  = phase ? 64 : 256;

    int rt = blockIdx.x;
    int st0 = blockIdx.y * 32;           // first sub-tile of this chunk

    auto fill = [&](int s) {
        unsigned slotb = smb + (unsigned)((s % 3) * SLOT_BYTES);
        const char* asrc = (const char*)(Aop) + ((size_t)(rt * nst + st0 + s * 2) << 14);
#pragma unroll
        for (int q = 0; q < 8; q++) {
            int idx = tid + q * 256;     // 2048 chunks of 16B = 32KB
            CP16(slotb + idx * 16, asrc + idx * 16);
        }
        const char* bsrc = (const char*)(Bop) + ((size_t)(st0 + s * 2) << 11);
        CP16(slotb + SLOT_B0 + tid * 16, bsrc + tid * 16);   // 4KB linear
        CP_COMMIT();
    };

    float acc[2][4];
#pragma unroll
    for (int nt = 0; nt < 2; nt++)
#pragma unroll
        for (int z = 0; z < 4; z++) acc[nt][z] = 0.f;

    fill(0); fill(1);

    int l8 = lane & 7;
    int lq = lane >> 3;

    for (int s = 0; s < NSTEPS; s++) {
        CP_WAIT1();
        __syncthreads();

        int ns = s + 2;
        if (ns < NSTEPS) { fill(ns); } else { CP_COMMIT(); }

        unsigned slotb = smb + (unsigned)((s % 3) * SLOT_BYTES);

#pragma unroll
        for (int kk = 0; kk < 8; kk++) {
            unsigned abase = slotb + ((kk < 4) ? SLOT_A0 : SLOT_A1);
            unsigned bbase = slotb + ((kk < 4) ? SLOT_B0 : SLOT_B1);
            int k4 = kk & 3;

            unsigned brow = (lq >> 1) * 8 + l8;
            unsigned bcol = k4 * 32 + (lq & 1) * 16;
            unsigned b0, b1, b2, b3;
            LDM_X4(b0, b1, b2, b3, bbase + SWZ(brow * 128 + bcol));

            unsigned arow = wid * 16 + (lq & 1) * 8 + l8;
            unsigned acol = k4 * 32 + (lq >> 1) * 16;
            unsigned a0, a1, a2, a3;
            LDM_X4(a0, a1, a2, a3, abase + SWZ(arow * 128 + acol));

            MMA16816(acc[0], a0, a1, a2, a3, b0, b1);   // hi batches
            MMA16816(acc[1], a0, a1, a2, a3, b2, b3);   // lo batches
        }
    }

    // ---- epilogue: fold hi + lo/2048, write partials ----
    int g = lane >> 2, t4 = lane & 3;
    int row = rt * 128 + wid * 16 + g;
    const float is = 1.f / 2048.f;
    float* d0 = outp + ((size_t)blockIdx.y * Mtot + row) * 8 + t4 * 2;
    float* d1 = outp + ((size_t)blockIdx.y * Mtot + row + 8) * 8 + t4 * 2;
    *reinterpret_cast<float2*>(d0) = make_float2(
        acc[0][0] + acc[1][0] * is, acc[0][1] + acc[1][1] * is);
    *reinterpret_cast<float2*>(d1) = make_float2(
        acc[0][2] + acc[1][2] * is, acc[0][3] + acc[1][3] * is);
}

// ---------------- r prep: r = sum(rpart) - meas -> staged hi/lo fp16 ---------
__global__ void k_rprep(const float* __restrict__ meas) {
    int idx = blockIdx.x * blockDim.x + threadIdx.x;   // 32768
    int b = idx >> 12, i = idx & 4095;
    float v = -meas[b * MM + i];
#pragma unroll
    for (int kc = 0; kc < KC1; kc++)
        v += g_rpart[((size_t)kc * MM + i) * 8 + b];
    __half hi = __float2half_rn(v);
    float  lo = (v - __half2float(hi)) * 2048.f;
    int c = i & 63;
    char* blk = (char*)g_r16 + ((size_t)(i >> 6) << 11);
    unsigned cpart = (unsigned)(((c >> 3) << 4));
    *reinterpret_cast<__half*>(blk + SWZ((unsigned)(b * 128) + cpart) + (c & 7) * 2) = hi;
    *reinterpret_cast<__half*>(blk + SWZ((unsigned)((b + 8) * 128) + cpart) + (c & 7) * 2) =
        __float2half_rn(lo);
}

// ---------------- finish: x = t - grad ; xbar = 2x - xbar_old ----------------
__global__ void k_fin() {
    int idx = blockIdx.x * blockDim.x + threadIdx.x;
    if (idx >= BN) return;
    int b = idx >> 14;
    int j = idx & (NN - 1);
    float s = 0.f;
#pragma unroll
    for (int kc = 0; kc < KC2; kc++)
        s += g_gpart[((size_t)kc * NN + j) * 8 + b];
    float xn = g_t[idx] - s;
    float xbo = g_xbar[idx];
    g_x[idx] = xn;
    g_xbar[idx] = 2.f * xn - xbo;
}

// ---------------- output copy ----------------
__global__ void k_copy(float* __restrict__ out) {
    int idx = blockIdx.x * blockDim.x + threadIdx.x;
    if (idx < BN) out[idx] = g_x[idx];
}

// ---------------- launch ----------------
extern "C" void kernel_launch(void* const* d_in, const int* in_sizes, int n_in,
                              void* d_out, int out_size) {
    const float* meas = (const float*)d_in[0];
    const float* A    = (const float*)d_in[1];
    if (n_in >= 2 && in_sizes[0] != BB * MM) {
        meas = (const float*)d_in[1];
        A    = (const float*)d_in[0];
    }
    float* out = (float*)d_out;

    cudaFuncSetAttribute(k_mma, cudaFuncAttributeMaxDynamicSharedMemorySize, SM_TOTAL);

    k_setupA<<<dim3(256, 32), 256>>>(A);
    k_setupAT<<<dim3(64, 128), 256>>>(A);
    k_zero<<<BN / 256, 256>>>();

    for (int it = 0; it < ITERS; it++) {
        int bi = it & 1;
        k_tv<<<BN / 256, 256>>>(bi);
        k_mma<<<dim3(MM / 128, KC1), 256, SM_TOTAL>>>(0);
        k_rprep<<<(MM * 8) / 256, 256>>>(meas);
        k_mma<<<dim3(NN / 128, KC2), 256, SM_TOTAL>>>(1);
        k_fin<<<BN / 256, 256>>>();
    }
    k_copy<<<BN / 256, 256>>>(out);
}

// round 17
// speedup vs baseline: 1.1603x; 1.0046x over previous
#include <cuda_runtime.h>
#include <cuda_fp16.h>
#include <cstdint>

#define BB   8
#define MM   4096
#define NN   16384
#define HH   128
#define WW   128
#define BN   (BB*NN)
#define TAUF 0.01f
#define EPSF 1e-8f
#define ITERS 100

#define KC1    8            // phase-1 K chunks (16384/8 = 2048)
#define KC2    2            // phase-2 K chunks (4096/2 = 2048)
#define KCHUNK 2048
#define NSTEPS 16           // KCHUNK / 128 cols per stage

// smem: 3 slots x 36KB; slot = A 32KB (2 subtiles contiguous) + B 4KB
#define SLOT_A0   0
#define SLOT_A1   16384
#define SLOT_B0   32768
#define SLOT_B1   34816
#define SLOT_BYTES 36864
#define SM_TOTAL  (3 * SLOT_BYTES)     // 108 KB -> 2 CTAs/SM

// ---------------- device state (no allocations allowed) ----------------
// A stored as pre-swizzled 16KB sub-tile blocks, consumption order:
//   g_Ah : block (rt, st) = rt*256 + st; rt in [0,32), st in [0,256)
//   g_AhT: block (rt, st) = rt*64  + st; rt in [0,128), st in [0,64)
__device__ __half g_Ah [(size_t)MM * NN];
__device__ __half g_AhT[(size_t)MM * NN];
__device__ float  g_x[BN];
__device__ float  g_xbar[BN];
__device__ float  g_t[BN];
__device__ float  g_yb[2][2][BN];
// B stored as pre-swizzled 2KB blocks (16 rows x 64 cols): t16: 256 blocks, r16: 64
__device__ __half g_t16[(size_t)16 * NN];
__device__ __half g_r16[(size_t)16 * MM];
__device__ float  g_rpart[(size_t)KC1 * MM * 8];   // [kc][i][b]
__device__ float  g_gpart[(size_t)KC2 * NN * 8];   // [kc][j][b]

// ---------------- helpers ----------------
#define SWZ(o) ((o) ^ (((o) >> 3) & 0x70))

#define CP16(DST, SRC) \
    asm volatile("cp.async.cg.shared.global [%0], [%1], 16;" :: "r"(DST), "l"(SRC))
#define CP_COMMIT() asm volatile("cp.async.commit_group;" ::: "memory")
#define CP_WAIT1()  asm volatile("cp.async.wait_group 1;"  ::: "memory")

#define LDM_X4(R0, R1, R2, R3, ADDR)                                          \
    asm volatile("ldmatrix.sync.aligned.m8n8.x4.shared.b16 {%0,%1,%2,%3}, [%4];" \
                 : "=r"(R0), "=r"(R1), "=r"(R2), "=r"(R3) : "r"(ADDR))

#define MMA16816(C, A0, A1, A2, A3, B0, B1)                                   \
    asm volatile("mma.sync.aligned.m16n8k16.row.col.f32.f16.f16.f32 "         \
                 "{%0,%1,%2,%3}, {%4,%5,%6,%7}, {%8,%9}, {%0,%1,%2,%3};"      \
                 : "+f"((C)[0]), "+f"((C)[1]), "+f"((C)[2]), "+f"((C)[3])     \
                 : "r"(A0), "r"(A1), "r"(A2), "r"(A3), "r"(B0), "r"(B1))

__device__ __forceinline__ uint4 pack8h(float4 f0, float4 f1) {
    __half2 h0 = __floats2half2_rn(f0.x, f0.y);
    __half2 h1 = __floats2half2_rn(f0.z, f0.w);
    __half2 h2 = __floats2half2_rn(f1.x, f1.y);
    __half2 h3 = __floats2half2_rn(f1.z, f1.w);
    uint4 o;
    o.x = *reinterpret_cast<unsigned*>(&h0);
    o.y = *reinterpret_cast<unsigned*>(&h1);
    o.z = *reinterpret_cast<unsigned*>(&h2);
    o.w = *reinterpret_cast<unsigned*>(&h3);
    return o;
}

// ---------------- setup: A fp32 -> staged swizzled fp16 blocks ---------------
// grid (256 st, 32 rt), 256 threads; thread: row r = t>>1, 32 cols.
__global__ void k_setupA(const float* __restrict__ A) {
    int st = blockIdx.x, rt = blockIdx.y, t = threadIdx.x;
    int r = t >> 1;
    int cbase = (t & 1) * 32;
    const float* src = A + (size_t)(rt * 128 + r) * NN + st * 64 + cbase;
    char* dst = (char*)g_Ah + ((size_t)(rt * 256 + st) << 14);
#pragma unroll
    for (int cg = 0; cg < 4; cg++) {
        float4 f0 = *reinterpret_cast<const float4*>(src + cg * 8);
        float4 f1 = *reinterpret_cast<const float4*>(src + cg * 8 + 4);
        int c0 = cbase + cg * 8;
        *reinterpret_cast<uint4*>(dst + SWZ((unsigned)(r * 128 + ((c0 >> 3) << 4)))) =
            pack8h(f0, f1);
    }
}

// grid (64 st, 128 rt), 256 threads; smem-transposed. Block element (r,c) =
// A[st*64 + c][rt*128 + r].
__global__ void k_setupAT(const float* __restrict__ A) {
    __shared__ __half tile[64][132];
    int st = blockIdx.x, rt = blockIdx.y, t = threadIdx.x;
    int jl = t >> 2;                 // source row 0..63
    int iq = (t & 3) * 32;           // i offset
    const float* src = A + (size_t)(st * 64 + jl) * NN + rt * 128 + iq;
#pragma unroll
    for (int g = 0; g < 8; g++) {
        float4 f = *reinterpret_cast<const float4*>(src + g * 4);
        tile[jl][iq + g * 4 + 0] = __float2half_rn(f.x);
        tile[jl][iq + g * 4 + 1] = __float2half_rn(f.y);
        tile[jl][iq + g * 4 + 2] = __float2half_rn(f.z);
        tile[jl][iq + g * 4 + 3] = __float2half_rn(f.w);
    }
    __syncthreads();
    char* dst = (char*)g_AhT + ((size_t)(rt * 64 + st) << 14);
#pragma unroll
    for (int qq = 0; qq < 4; qq++) {
        int id = t + qq * 256;
        int r = id >> 3, c16 = id & 7;
        float4 f0, f1;
        f0.x = __half2float(tile[c16 * 8 + 0][r]);
        f0.y = __half2float(tile[c16 * 8 + 1][r]);
        f0.z = __half2float(tile[c16 * 8 + 2][r]);
        f0.w = __half2float(tile[c16 * 8 + 3][r]);
        f1.x = __half2float(tile[c16 * 8 + 4][r]);
        f1.y = __half2float(tile[c16 * 8 + 5][r]);
        f1.z = __half2float(tile[c16 * 8 + 6][r]);
        f1.w = __half2float(tile[c16 * 8 + 7][r]);
        *reinterpret_cast<uint4*>(dst + SWZ((unsigned)(r * 128 + c16 * 16))) =
            pack8h(f0, f1);
    }
}

// ---------------- zero init ----------------
__global__ void k_zero() {
    int idx = blockIdx.x * blockDim.x + threadIdx.x;
    if (idx < BN) {
        g_x[idx] = 0.f; g_xbar[idx] = 0.f;
        g_yb[0][0][idx] = 0.f; g_yb[0][1][idx] = 0.f;
    }
}

// ---------------- TV stencil + staged t16 hi/lo emit ----------------
__global__ void k_tv(int bi) {
    int idx = blockIdx.x * blockDim.x + threadIdx.x;
    if (idx >= BN) return;
    int p = idx & (NN - 1);
    int i = p >> 7;
    int j = p & 127;
    int b = idx >> 14;

    const float* yx = g_yb[bi][0];
    const float* yy = g_yb[bi][1];
    float*       oyx = g_yb[bi ^ 1][0];
    float*       oyy = g_yb[bi ^ 1][1];

    float yxv = yx[idx];
    float yyv = yy[idx];

    float dx = (j > 0) ? (yxv - yx[idx - 1])  : 0.f;
    float dy = (i > 0) ? (yyv - yy[idx - WW]) : 0.f;
    float t = g_x[idx] - TAUF * (dx + dy);
    g_t[idx] = t;

    __half hi = __float2half_rn(t);
    float  lo = (t - __half2float(hi)) * 2048.f;
    // staged write: block = p>>6 (2KB), row b (hi) / b+8 (lo), col c = p&63
    int c = p & 63;
    char* blk = (char*)g_t16 + ((size_t)(p >> 6) << 11);
    unsigned cpart = (unsigned)(((c >> 3) << 4));
    *reinterpret_cast<__half*>(blk + SWZ((unsigned)(b * 128) + cpart) + (c & 7) * 2) = hi;
    *reinterpret_cast<__half*>(blk + SWZ((unsigned)((b + 8) * 128) + cpart) + (c & 7) * 2) =
        __float2half_rn(lo);

    float xb = g_xbar[idx];
    float gx = (j < WW - 1) ? (xb - g_xbar[idx + 1])  : 0.f;
    float gy = (i < HH - 1) ? (xb - g_xbar[idx + WW]) : 0.f;

    float nyx = yxv + TAUF * gx;
    float nyy = yyv + TAUF * gy;
    float denom = fmaxf(fabsf(nyx), fabsf(nyy)) + EPSF;
    float inv = 1.f / denom;
    oyx[idx] = nyx * inv;
    oyy[idx] = nyy * inv;
}

// ---------------- unified HMMA GEMV kernel -----------------------------------
// Identical consumption to R15 (256 thr, 8 warps x 16 rows, 3-slot ring).
// Fill is now a LINEAR copy: A = one contiguous 32KB block pair; B = 4KB pair.
__global__ __launch_bounds__(256) void k_mma(int phase) {
    extern __shared__ char sm[];
    unsigned smb = (unsigned)__cvta_generic_to_shared(sm);
    int tid = threadIdx.x, wid = tid >> 5, lane = tid & 31;

    const __half* Aop = phase ? g_AhT : g_Ah;
    const __half* Bop = phase ? g_r16 : g_t16;
    float*        outp = phase ? g_gpart : g_rpart;
    const int Mtot = phase ? NN : MM;
    const int nst  = phase ? 64 : 256;

    int rt = blockIdx.x;
    int st0 = blockIdx.y * 32;           // first sub-tile of this chunk

    auto fill = [&](int s) {
        unsigned slotb = smb + (unsigned)((s % 3) * SLOT_BYTES);
        const char* asrc = (const char*)(Aop) + ((size_t)(rt * nst + st0 + s * 2) << 14);
#pragma unroll
        for (int q = 0; q < 8; q++) {
            int idx = tid + q * 256;     // 2048 chunks of 16B = 32KB
            CP16(slotb + idx * 16, asrc + idx * 16);
        }
        const char* bsrc = (const char*)(Bop) + ((size_t)(st0 + s * 2) << 11);
        CP16(slotb + SLOT_B0 + tid * 16, bsrc + tid * 16);   // 4KB linear
        CP_COMMIT();
    };

    float acc[2][4];
#pragma unroll
    for (int nt = 0; nt < 2; nt++)
#pragma unroll
        for (int z = 0; z < 4; z++) acc[nt][z] = 0.f;

    fill(0); fill(1);

    int l8 = lane & 7;
    int lq = lane >> 3;

    for (int s = 0; s < NSTEPS; s++) {
        CP_WAIT1();
        __syncthreads();

        int ns = s + 2;
        if (ns < NSTEPS) { fill(ns); } else { CP_COMMIT(); }

        unsigned slotb = smb + (unsigned)((s % 3) * SLOT_BYTES);

#pragma unroll
        for (int kk = 0; kk < 8; kk++) {
            unsigned abase = slotb + ((kk < 4) ? SLOT_A0 : SLOT_A1);
            unsigned bbase = slotb + ((kk < 4) ? SLOT_B0 : SLOT_B1);
            int k4 = kk & 3;

            unsigned brow = (lq >> 1) * 8 + l8;
            unsigned bcol = k4 * 32 + (lq & 1) * 16;
            unsigned b0, b1, b2, b3;
            LDM_X4(b0, b1, b2, b3, bbase + SWZ(brow * 128 + bcol));

            unsigned arow = wid * 16 + (lq & 1) * 8 + l8;
            unsigned acol = k4 * 32 + (lq >> 1) * 16;
            unsigned a0, a1, a2, a3;
            LDM_X4(a0, a1, a2, a3, abase + SWZ(arow * 128 + acol));

            MMA16816(acc[0], a0, a1, a2, a3, b0, b1);   // hi batches
            MMA16816(acc[1], a0, a1, a2, a3, b2, b3);   // lo batches
        }
    }

    // ---- epilogue: fold hi + lo/2048, write partials ----
    int g = lane >> 2, t4 = lane & 3;
    int row = rt * 128 + wid * 16 + g;
    const float is = 1.f / 2048.f;
    float* d0 = outp + ((size_t)blockIdx.y * Mtot + row) * 8 + t4 * 2;
    float* d1 = outp + ((size_t)blockIdx.y * Mtot + row + 8) * 8 + t4 * 2;
    *reinterpret_cast<float2*>(d0) = make_float2(
        acc[0][0] + acc[1][0] * is, acc[0][1] + acc[1][1] * is);
    *reinterpret_cast<float2*>(d1) = make_float2(
        acc[0][2] + acc[1][2] * is, acc[0][3] + acc[1][3] * is);
}

// ---------------- r prep: r = sum(rpart) - meas -> staged hi/lo fp16 ---------
__global__ void k_rprep(const float* __restrict__ meas) {
    int idx = blockIdx.x * blockDim.x + threadIdx.x;   // 32768
    int b = idx >> 12, i = idx & 4095;
    float v = -meas[b * MM + i];
#pragma unroll
    for (int kc = 0; kc < KC1; kc++)
        v += g_rpart[((size_t)kc * MM + i) * 8 + b];
    __half hi = __float2half_rn(v);
    float  lo = (v - __half2float(hi)) * 2048.f;
    int c = i & 63;
    char* blk = (char*)g_r16 + ((size_t)(i >> 6) << 11);
    unsigned cpart = (unsigned)(((c >> 3) << 4));
    *reinterpret_cast<__half*>(blk + SWZ((unsigned)(b * 128) + cpart) + (c & 7) * 2) = hi;
    *reinterpret_cast<__half*>(blk + SWZ((unsigned)((b + 8) * 128) + cpart) + (c & 7) * 2) =
        __float2half_rn(lo);
}

// ---------------- finish: x = t - grad ; xbar = 2x - xbar_old ----------------
__global__ void k_fin() {
    int idx = blockIdx.x * blockDim.x + threadIdx.x;
    if (idx >= BN) return;
    int b = idx >> 14;
    int j = idx & (NN - 1);
    float s = 0.f;
#pragma unroll
    for (int kc = 0; kc < KC2; kc++)
        s += g_gpart[((size_t)kc * NN + j) * 8 + b];
    float xn = g_t[idx] - s;
    float xbo = g_xbar[idx];
    g_x[idx] = xn;
    g_xbar[idx] = 2.f * xn - xbo;
}

// ---------------- output copy ----------------
__global__ void k_copy(float* __restrict__ out) {
    int idx = blockIdx.x * blockDim.x + threadIdx.x;
    if (idx < BN) out[idx] = g_x[idx];
}

// ---------------- launch ----------------
extern "C" void kernel_launch(void* const* d_in, const int* in_sizes, int n_in,
                              void* d_out, int out_size) {
    const float* meas = (const float*)d_in[0];
    const float* A    = (const float*)d_in[1];
    if (n_in >= 2 && in_sizes[0] != BB * MM) {
        meas = (const float*)d_in[1];
        A    = (const float*)d_in[0];
    }
    float* out = (float*)d_out;

    cudaFuncSetAttribute(k_mma, cudaFuncAttributeMaxDynamicSharedMemorySize, SM_TOTAL);

    k_setupA<<<dim3(256, 32), 256>>>(A);
    k_setupAT<<<dim3(64, 128), 256>>>(A);
    k_zero<<<BN / 256, 256>>>();

    for (int it = 0; it < ITERS; it++) {
        int bi = it & 1;
        k_tv<<<BN / 256, 256>>>(bi);
        k_mma<<<dim3(MM / 128, KC1), 256, SM_TOTAL>>>(0);
        k_rprep<<<(MM * 8) / 256, 256>>>(meas);
        k_mma<<<dim3(NN / 128, KC2), 256, SM_TOTAL>>>(1);
        k_fin<<<BN / 256, 256>>>();
    }
    k_copy<<<BN / 256, 256>>>(out);
}